// round 6
// baseline (speedup 1.0000x reference)
#include <cuda_runtime.h>

// Problem constants: B=2, H=16, T=8192, D=64, M=8
#define TT 8192
#define BB 2
#define HH 16
#define DD 64
#define MM 8

#define THREADS 128          // 4 warps, 8 lanes per row -> 16 rows per pass
#define PASSES 16            // 256 rows per block
#define ROWS_PER_BLOCK (PASSES * (THREADS / 8))   // 256

// cos/sin table: per t, 32 pairs (cos, sin) interleaved -> 64 floats per t. 2 MB.
__device__ float g_tab[TT * DD];
// Compact-WY factors per head: P = I + W * U^T  (W columns include the -2)
__device__ float g_U[HH * MM * DD];
__device__ float g_W[HH * MM * DD];

// ---------------------------------------------------------------------------
// Prep kernel 1: accurate sincosf table
// ---------------------------------------------------------------------------
__global__ void build_table_kernel(const float* __restrict__ pos,
                                   const float* __restrict__ freq) {
    int idx = blockIdx.x * blockDim.x + threadIdx.x;   // t*32 + j
    if (idx >= TT * 32) return;
    int t = idx >> 5;
    int j = idx & 31;
    float a = pos[t] * freq[j];
    float s, c;
    sincosf(a, &s, &c);
    g_tab[t * DD + 2 * j]     = c;
    g_tab[t * DD + 2 * j + 1] = s;
}

// ---------------------------------------------------------------------------
// Prep kernel 2: build U (normalized reflectors) and compact-WY W per head.
//   P_0 = I - 2 u_0 u_0^T          -> w_0 = -2 u_0
//   P_k = P_{k-1} (I - 2 u_k u_k^T) -> w_k = -2 (u_k + sum_{i<k} (u_i.u_k) w_i)
// One block per head, 64 threads (thread j owns vector component j).
// ---------------------------------------------------------------------------
__global__ void build_uw_kernel(const float* __restrict__ V) {
    const int h    = blockIdx.x;
    const int j    = threadIdx.x;      // 0..63
    const int lane = j & 31;
    const int w    = j >> 5;           // warp id 0/1

    __shared__ float sU[MM][DD];
    __shared__ float sW[MM][DD];
    __shared__ float red[2][MM];       // per-warp reduction partials

    // load V[h][m][j]
    float v[MM];
    #pragma unroll
    for (int m = 0; m < MM; m++)
        v[m] = V[((size_t)h * MM + m) * DD + j];

    // norms (8 reductions over 64 threads)
    #pragma unroll
    for (int m = 0; m < MM; m++) {
        float p = v[m] * v[m];
        p += __shfl_xor_sync(0xffffffffu, p, 16);
        p += __shfl_xor_sync(0xffffffffu, p, 8);
        p += __shfl_xor_sync(0xffffffffu, p, 4);
        p += __shfl_xor_sync(0xffffffffu, p, 2);
        p += __shfl_xor_sync(0xffffffffu, p, 1);
        if (lane == 0) red[w][m] = p;
    }
    __syncthreads();
    #pragma unroll
    for (int m = 0; m < MM; m++) {
        float r = rsqrtf(red[0][m] + red[1][m] + 1e-16f);  // EPS^2, EPS=1e-8
        sU[m][j] = v[m] * r;
    }
    __syncthreads();

    // w_0
    sW[0][j] = -2.0f * sU[0][j];
    __syncthreads();

    for (int k = 1; k < MM; k++) {
        float uk = sU[k][j];
        // dots d_i = u_i . u_k for i < k
        for (int i = 0; i < k; i++) {
            float p = sU[i][j] * uk;
            p += __shfl_xor_sync(0xffffffffu, p, 16);
            p += __shfl_xor_sync(0xffffffffu, p, 8);
            p += __shfl_xor_sync(0xffffffffu, p, 4);
            p += __shfl_xor_sync(0xffffffffu, p, 2);
            p += __shfl_xor_sync(0xffffffffu, p, 1);
            if (lane == 0) red[w][i] = p;
        }
        __syncthreads();
        float s = uk;
        for (int i = 0; i < k; i++) {
            float d = red[0][i] + red[1][i];
            s = fmaf(d, sW[i][j], s);
        }
        __syncthreads();              // red reads done before next-iter writes
        sW[k][j] = -2.0f * s;
        __syncthreads();
    }

    // store U, W
    #pragma unroll
    for (int m = 0; m < MM; m++) {
        g_U[((size_t)h * MM + m) * DD + j] = sU[m][j];
        g_W[((size_t)h * MM + m) * DD + j] = sW[m][j];
    }
}

// ---------------------------------------------------------------------------
// Main kernel: z_out = RoPE( z + W (U^T z) ), 8 lanes per row.
// U slice in registers; W in shared memory (broadcast LDS.128 reads).
// ---------------------------------------------------------------------------
__global__ void __launch_bounds__(THREADS, 5)
hh_rope_kernel(const float* __restrict__ q,
               const float* __restrict__ k,
               float* __restrict__ out) {
    const int bh   = blockIdx.y;          // b*H + h   (0..31)
    const int h    = bh & (HH - 1);
    const int tsel = blockIdx.z;          // 0 = q, 1 = k
    const int t0   = blockIdx.x * ROWS_PER_BLOCK;

    const int tid   = threadIdx.x;
    const int lane8 = tid & 7;            // which 8-float chunk of the row

    // ---- stage W[h] into shared memory (512 floats = 2 KB) ----
    __shared__ float s_W[MM * DD];
    {
        const float4* src = (const float4*)(g_W + (size_t)h * MM * DD);
        ((float4*)s_W)[tid] = src[tid];   // 128 threads x float4 = 512 floats
    }

    // ---- preload this lane's slice of all 8 unit reflectors into registers ----
    float4 uA[MM], uB[MM];
    {
        const float4* Up = (const float4*)(g_U + (size_t)h * MM * DD);
        #pragma unroll
        for (int m = 0; m < MM; m++) {
            uA[m] = Up[m * 16 + lane8 * 2];
            uB[m] = Up[m * 16 + lane8 * 2 + 1];
        }
    }
    __syncthreads();

    const float* src = (tsel ? k : q) + ((size_t)bh * TT + t0) * DD;
    float*       dst = out + ((size_t)tsel * BB * HH * TT + (size_t)bh * TT + t0) * DD;
    const float4* src4 = (const float4*)src;
    float4*       dst4 = (float4*)dst;
    const float4* tab4 = (const float4*)(g_tab) + (size_t)t0 * 16;  // 16 float4 per t
    const float4* sW4  = (const float4*)s_W;

    for (int p = 0; p < PASSES; p++) {
        const int f = (p * THREADS + tid) * 2;   // float4 index (coalesced)

        float4 z0 = src4[f];
        float4 z1 = src4[f + 1];
        float4 c0 = tab4[f];        // (cos,sin) pairs 0,1 of this chunk
        float4 c1 = tab4[f + 1];    // pairs 2,3

        // ---- 8 independent partial dots t[m] = u_m . z (this lane's 8 elems)
        float t[MM];
        #pragma unroll
        for (int m = 0; m < MM; m++) {
            float d =           z0.x * uA[m].x;
            d = fmaf(z0.y, uA[m].y, d);
            d = fmaf(z0.z, uA[m].z, d);
            d = fmaf(z0.w, uA[m].w, d);
            d = fmaf(z1.x, uB[m].x, d);
            d = fmaf(z1.y, uB[m].y, d);
            d = fmaf(z1.z, uB[m].z, d);
            d = fmaf(z1.w, uB[m].w, d);
            t[m] = d;
        }
        // ---- 8 independent butterfly reductions across the 8-lane group
        #pragma unroll
        for (int m = 0; m < MM; m++) {
            t[m] += __shfl_xor_sync(0xffffffffu, t[m], 1);
            t[m] += __shfl_xor_sync(0xffffffffu, t[m], 2);
            t[m] += __shfl_xor_sync(0xffffffffu, t[m], 4);
        }
        // ---- z += W t   (W columns already carry the -2 factors)
        #pragma unroll
        for (int m = 0; m < MM; m++) {
            float4 wA = sW4[m * 16 + lane8 * 2];
            float4 wB = sW4[m * 16 + lane8 * 2 + 1];
            z0.x = fmaf(wA.x, t[m], z0.x);
            z0.y = fmaf(wA.y, t[m], z0.y);
            z0.z = fmaf(wA.z, t[m], z0.z);
            z0.w = fmaf(wA.w, t[m], z0.w);
            z1.x = fmaf(wB.x, t[m], z1.x);
            z1.y = fmaf(wB.y, t[m], z1.y);
            z1.z = fmaf(wB.z, t[m], z1.z);
            z1.w = fmaf(wB.w, t[m], z1.w);
        }

        // ---- RoPE rotate: pairs (x,y) and (z,w)
        float4 o0, o1;
        o0.x = z0.x * c0.x - z0.y * c0.y;
        o0.y = fmaf(z0.x, c0.y, z0.y * c0.x);
        o0.z = z0.z * c0.z - z0.w * c0.w;
        o0.w = fmaf(z0.z, c0.w, z0.w * c0.z);
        o1.x = z1.x * c1.x - z1.y * c1.y;
        o1.y = fmaf(z1.x, c1.y, z1.y * c1.x);
        o1.z = z1.z * c1.z - z1.w * c1.w;
        o1.w = fmaf(z1.z, c1.w, z1.w * c1.z);

        dst4[f]     = o0;
        dst4[f + 1] = o1;
    }
}

// ---------------------------------------------------------------------------
// Launch
// ---------------------------------------------------------------------------
extern "C" void kernel_launch(void* const* d_in, const int* in_sizes, int n_in,
                              void* d_out, int out_size) {
    const float* q    = (const float*)d_in[0];
    const float* k    = (const float*)d_in[1];
    const float* V    = (const float*)d_in[2];
    const float* pos  = (const float*)d_in[3];
    const float* freq = (const float*)d_in[4];
    float* out = (float*)d_out;

    // 1) cos/sin table
    {
        int n = TT * 32;
        build_table_kernel<<<(n + 255) / 256, 256>>>(pos, freq);
    }
    // 2) compact-WY factors per head
    build_uw_kernel<<<HH, DD>>>(V);

    // 3) main fused kernel: grid = (t-chunks, b*h, q/k)
    dim3 grid(TT / ROWS_PER_BLOCK, BB * HH, 2);   // (32, 32, 2)
    hh_rope_kernel<<<grid, THREADS>>>(q, k, out);
}

// round 8
// speedup vs baseline: 1.3696x; 1.3696x over previous
#include <cuda_runtime.h>

// Problem constants: B=2, H=16, T=8192, D=64, M=8
#define TT 8192
#define BB 2
#define HH 16
#define DD 64
#define MM 8

#define THREADS 128          // 4 warps, 8 lanes per row -> 16 rows per pass
#define PASSES 16            // 256 rows per block
#define ROWS_PER_BLOCK (PASSES * (THREADS / 8))   // 256

// cos/sin table: per t, 32 pairs (cos, sin) interleaved -> 64 floats per t. 2 MB.
__device__ float g_tab[TT * DD];
// Compact-WY factors per head: P = I + W * U^T  (W columns include the -2)
__device__ float g_U[HH * MM * DD];
__device__ float g_W[HH * MM * DD];

// ---------------------------------------------------------------------------
// Prep kernel 1: accurate sincosf table
// ---------------------------------------------------------------------------
__global__ void build_table_kernel(const float* __restrict__ pos,
                                   const float* __restrict__ freq) {
    int idx = blockIdx.x * blockDim.x + threadIdx.x;   // t*32 + j
    if (idx >= TT * 32) return;
    int t = idx >> 5;
    int j = idx & 31;
    float a = pos[t] * freq[j];
    float s, c;
    sincosf(a, &s, &c);
    g_tab[t * DD + 2 * j]     = c;
    g_tab[t * DD + 2 * j + 1] = s;
}

// ---------------------------------------------------------------------------
// Prep kernel 2: build U (normalized reflectors) and compact-WY W per head.
//   P_0 = I - 2 u_0 u_0^T          -> w_0 = -2 u_0
//   P_k = P_{k-1} (I - 2 u_k u_k^T) -> w_k = -2 (u_k + sum_{i<k} (u_i.u_k) w_i)
// One block per head, 64 threads (thread j owns vector component j).
// ---------------------------------------------------------------------------
__global__ void build_uw_kernel(const float* __restrict__ V) {
    const int h    = blockIdx.x;
    const int j    = threadIdx.x;      // 0..63
    const int lane = j & 31;
    const int w    = j >> 5;           // warp id 0/1

    __shared__ float sU[MM][DD];
    __shared__ float sW[MM][DD];
    __shared__ float red[2][MM];       // per-warp reduction partials

    // load V[h][m][j]
    float v[MM];
    #pragma unroll
    for (int m = 0; m < MM; m++)
        v[m] = V[((size_t)h * MM + m) * DD + j];

    // norms (8 reductions over 64 threads)
    #pragma unroll
    for (int m = 0; m < MM; m++) {
        float p = v[m] * v[m];
        p += __shfl_xor_sync(0xffffffffu, p, 16);
        p += __shfl_xor_sync(0xffffffffu, p, 8);
        p += __shfl_xor_sync(0xffffffffu, p, 4);
        p += __shfl_xor_sync(0xffffffffu, p, 2);
        p += __shfl_xor_sync(0xffffffffu, p, 1);
        if (lane == 0) red[w][m] = p;
    }
    __syncthreads();
    #pragma unroll
    for (int m = 0; m < MM; m++) {
        float r = rsqrtf(red[0][m] + red[1][m] + 1e-16f);  // EPS^2, EPS=1e-8
        sU[m][j] = v[m] * r;
    }
    __syncthreads();

    // w_0
    sW[0][j] = -2.0f * sU[0][j];
    __syncthreads();

    for (int k = 1; k < MM; k++) {
        float uk = sU[k][j];
        // dots d_i = u_i . u_k for i < k
        for (int i = 0; i < k; i++) {
            float p = sU[i][j] * uk;
            p += __shfl_xor_sync(0xffffffffu, p, 16);
            p += __shfl_xor_sync(0xffffffffu, p, 8);
            p += __shfl_xor_sync(0xffffffffu, p, 4);
            p += __shfl_xor_sync(0xffffffffu, p, 2);
            p += __shfl_xor_sync(0xffffffffu, p, 1);
            if (lane == 0) red[w][i] = p;
        }
        __syncthreads();
        float s = uk;
        for (int i = 0; i < k; i++) {
            float d = red[0][i] + red[1][i];
            s = fmaf(d, sW[i][j], s);
        }
        __syncthreads();              // red reads done before next-iter writes
        sW[k][j] = -2.0f * s;
        __syncthreads();
    }

    // store U, W
    #pragma unroll
    for (int m = 0; m < MM; m++) {
        g_U[((size_t)h * MM + m) * DD + j] = sU[m][j];
        g_W[((size_t)h * MM + m) * DD + j] = sW[m][j];
    }
}

// ---------------------------------------------------------------------------
// Main kernel: z_out = RoPE( z + W (U^T z) ), 8 lanes per row.
// BOTH U and W slices live in registers: the mainloop has no shared-memory
// traffic at all (MIO carries only the 24 shuffles per pass).
// ---------------------------------------------------------------------------
__global__ void __launch_bounds__(THREADS, 3)
hh_rope_kernel(const float* __restrict__ q,
               const float* __restrict__ k,
               float* __restrict__ out) {
    const int bh   = blockIdx.y;          // b*H + h   (0..31)
    const int h    = bh & (HH - 1);
    const int tsel = blockIdx.z;          // 0 = q, 1 = k
    const int t0   = blockIdx.x * ROWS_PER_BLOCK;

    const int tid   = threadIdx.x;
    const int lane8 = tid & 7;            // which 8-float chunk of the row

    // ---- preload this lane's slices of U and W into registers ----
    float4 uA[MM], uB[MM], wA[MM], wB[MM];
    {
        const float4* Up = (const float4*)(g_U + (size_t)h * MM * DD);
        const float4* Wp = (const float4*)(g_W + (size_t)h * MM * DD);
        #pragma unroll
        for (int m = 0; m < MM; m++) {
            uA[m] = Up[m * 16 + lane8 * 2];
            uB[m] = Up[m * 16 + lane8 * 2 + 1];
            wA[m] = Wp[m * 16 + lane8 * 2];
            wB[m] = Wp[m * 16 + lane8 * 2 + 1];
        }
    }

    const float* src = (tsel ? k : q) + ((size_t)bh * TT + t0) * DD;
    float*       dst = out + ((size_t)tsel * BB * HH * TT + (size_t)bh * TT + t0) * DD;
    const float4* src4 = (const float4*)src;
    float4*       dst4 = (float4*)dst;
    const float4* tab4 = (const float4*)(g_tab) + (size_t)t0 * 16;  // 16 float4 per t

    for (int p = 0; p < PASSES; p++) {
        const int f = (p * THREADS + tid) * 2;   // float4 index (coalesced)

        float4 z0 = src4[f];
        float4 z1 = src4[f + 1];
        float4 c0 = tab4[f];        // (cos,sin) pairs 0,1 of this chunk
        float4 c1 = tab4[f + 1];    // pairs 2,3

        // ---- 8 independent partial dots t[m] = u_m . z (this lane's 8 elems)
        float t[MM];
        #pragma unroll
        for (int m = 0; m < MM; m++) {
            float d =           z0.x * uA[m].x;
            d = fmaf(z0.y, uA[m].y, d);
            d = fmaf(z0.z, uA[m].z, d);
            d = fmaf(z0.w, uA[m].w, d);
            d = fmaf(z1.x, uB[m].x, d);
            d = fmaf(z1.y, uB[m].y, d);
            d = fmaf(z1.z, uB[m].z, d);
            d = fmaf(z1.w, uB[m].w, d);
            t[m] = d;
        }
        // ---- 8 independent butterfly reductions across the 8-lane group
        #pragma unroll
        for (int m = 0; m < MM; m++) {
            t[m] += __shfl_xor_sync(0xffffffffu, t[m], 1);
            t[m] += __shfl_xor_sync(0xffffffffu, t[m], 2);
            t[m] += __shfl_xor_sync(0xffffffffu, t[m], 4);
        }
        // ---- z += W t   (W columns already carry the -2 factors)
        #pragma unroll
        for (int m = 0; m < MM; m++) {
            z0.x = fmaf(wA[m].x, t[m], z0.x);
            z0.y = fmaf(wA[m].y, t[m], z0.y);
            z0.z = fmaf(wA[m].z, t[m], z0.z);
            z0.w = fmaf(wA[m].w, t[m], z0.w);
            z1.x = fmaf(wB[m].x, t[m], z1.x);
            z1.y = fmaf(wB[m].y, t[m], z1.y);
            z1.z = fmaf(wB[m].z, t[m], z1.z);
            z1.w = fmaf(wB[m].w, t[m], z1.w);
        }

        // ---- RoPE rotate: pairs (x,y) and (z,w)
        float4 o0, o1;
        o0.x = z0.x * c0.x - z0.y * c0.y;
        o0.y = fmaf(z0.x, c0.y, z0.y * c0.x);
        o0.z = z0.z * c0.z - z0.w * c0.w;
        o0.w = fmaf(z0.z, c0.w, z0.w * c0.z);
        o1.x = z1.x * c1.x - z1.y * c1.y;
        o1.y = fmaf(z1.x, c1.y, z1.y * c1.x);
        o1.z = z1.z * c1.z - z1.w * c1.w;
        o1.w = fmaf(z1.z, c1.w, z1.w * c1.z);

        dst4[f]     = o0;
        dst4[f + 1] = o1;
    }
}

// ---------------------------------------------------------------------------
// Launch
// ---------------------------------------------------------------------------
extern "C" void kernel_launch(void* const* d_in, const int* in_sizes, int n_in,
                              void* d_out, int out_size) {
    const float* q    = (const float*)d_in[0];
    const float* k    = (const float*)d_in[1];
    const float* V    = (const float*)d_in[2];
    const float* pos  = (const float*)d_in[3];
    const float* freq = (const float*)d_in[4];
    float* out = (float*)d_out;

    // 1) cos/sin table
    {
        int n = TT * 32;
        build_table_kernel<<<(n + 255) / 256, 256>>>(pos, freq);
    }
    // 2) compact-WY factors per head
    build_uw_kernel<<<HH, DD>>>(V);

    // 3) main fused kernel: grid = (t-chunks, b*h, q/k)
    dim3 grid(TT / ROWS_PER_BLOCK, BB * HH, 2);   // (32, 32, 2)
    hh_rope_kernel<<<grid, THREADS>>>(q, k, out);
}